// round 11
// baseline (speedup 1.0000x reference)
#include <cuda_runtime.h>

#define BATCH   8192
#define KDIM    256
#define EPSF    1e-10f
#define SW8     4
#define SW4     3

// Packed fp32x2 ops (Blackwell): only reachable via PTX.
#define FMA_F32X2(d, a, b, c) \
    asm("fma.rn.f32x2 %0, %1, %2, %3;" : "=l"(d) : "l"(a), "l"(b), "l"(c))
#define MUL_F32X2(d, a, b) \
    asm("mul.rn.f32x2 %0, %1, %2;" : "=l"(d) : "l"(a), "l"(b))
#define UNPACK_F32X2(lo, hi, in) do {                                   \
    unsigned _ulo, _uhi;                                                \
    asm("mov.b64 {%0, %1}, %2;" : "=r"(_ulo), "=r"(_uhi) : "l"(in));    \
    lo = __uint_as_float(_ulo); hi = __uint_as_float(_uhi);             \
} while (0)

__device__ __forceinline__ void rot_params(float al, float be, float ga,
                                           float& c, float& s) {
    float tau = (be - al) * __fdividef(0.5f, ga);
    float t = copysignf(1.f, tau) *
              __fdividef(1.f, fabsf(tau) + sqrtf(fmaf(tau, tau, 1.f)));
    t = (fabsf(ga) > 1e-30f) ? t : 0.f;
    c = rsqrtf(fmaf(t, t, 1.f));
    s = c * t;
}

// ---------------------------------------------------------------------------
// Fused kernel: one CTA per element.
//   Phase 1 (4 warps): cross-Gram blocks -> 96 floats in smem.
//     smem 0..63  M8[i][j] (o=i*8+j); 64..79 ML; 80..95 MR.
//   Phase 2 (warp 0 only; warps 1-3 exit): 8-lane one-sided Jacobi + entropy.
// Jacobi tails of early CTAs hide under later CTAs' gram phases.
// ---------------------------------------------------------------------------
__global__ __launch_bounds__(128)
void phi_q_fused(const float* __restrict__ sites, float* __restrict__ out) {
    const int b    = blockIdx.x;
    const int tid  = threadIdx.x;
    const int warp = tid >> 5;
    const int lane = tid & 31;

    __shared__ float G[96];

    // ---------------- Phase 1: Gram (identical math to R7/R10) ----------------
    // Row r = 256 floats = 64 x 16B. Lane owns 16B chunks (lane) and (lane+32).
    const ulonglong2* S2 = (const ulonglong2*)(sites + (size_t)b * (16 * KDIM));

    if (warp < 2) {
        // M8 rows i = warp*4..warp*4+3 vs rows 8..15 -> 32 outputs
        ulonglong2 Ar[4][2];
        #pragma unroll
        for (int a = 0; a < 4; a++) {
            Ar[a][0] = S2[(warp * 4 + a) * 64 + lane];
            Ar[a][1] = S2[(warp * 4 + a) * 64 + lane + 32];
        }
        unsigned long long acc[32];
        #pragma unroll
        for (int j = 0; j < 8; j++) {
            ulonglong2 B0 = S2[(8 + j) * 64 + lane];
            ulonglong2 B1 = S2[(8 + j) * 64 + lane + 32];
            #pragma unroll
            for (int a = 0; a < 4; a++) {
                unsigned long long& d = acc[a * 8 + j];
                MUL_F32X2(d, Ar[a][0].x, B0.x);
                FMA_F32X2(d, Ar[a][0].y, B0.y, d);
                FMA_F32X2(d, Ar[a][1].x, B1.x, d);
                FMA_F32X2(d, Ar[a][1].y, B1.y, d);
            }
        }
        float v[32];
        #pragma unroll
        for (int o = 0; o < 32; o++) {
            float lo, hi; UNPACK_F32X2(lo, hi, acc[o]);
            v[o] = lo + hi;
        }
        // Multi-value tree reduce: lane l ends with output l in v[0].
        #pragma unroll
        for (int stride = 16; stride >= 1; stride >>= 1) {
            #pragma unroll
            for (int j = 0; j < stride; j++) {
                float send = (lane & stride) ? v[j] : v[j + stride];
                float recv = __shfl_xor_sync(0xffffffffu, send, stride);
                v[j] = ((lane & stride) ? v[j + stride] : v[j]) + recv;
            }
        }
        G[warp * 32 + lane] = v[0];
    } else {
        // warp2: ML (rows 0-3 x 4-7); warp3: MR (rows 8-11 x 12-15) -> 16 outputs
        const int ra   = (warp == 2) ? 0 : 8;
        const int base = (warp == 2) ? 64 : 80;
        ulonglong2 Ar[4][2];
        #pragma unroll
        for (int a = 0; a < 4; a++) {
            Ar[a][0] = S2[(ra + a) * 64 + lane];
            Ar[a][1] = S2[(ra + a) * 64 + lane + 32];
        }
        unsigned long long acc[16];
        #pragma unroll
        for (int j = 0; j < 4; j++) {
            ulonglong2 B0 = S2[(ra + 4 + j) * 64 + lane];
            ulonglong2 B1 = S2[(ra + 4 + j) * 64 + lane + 32];
            #pragma unroll
            for (int a = 0; a < 4; a++) {
                unsigned long long& d = acc[a * 4 + j];
                MUL_F32X2(d, Ar[a][0].x, B0.x);
                FMA_F32X2(d, Ar[a][0].y, B0.y, d);
                FMA_F32X2(d, Ar[a][1].x, B1.x, d);
                FMA_F32X2(d, Ar[a][1].y, B1.y, d);
            }
        }
        float v[16];
        #pragma unroll
        for (int o = 0; o < 16; o++) {
            float lo, hi; UNPACK_F32X2(lo, hi, acc[o]);
            v[o] = lo + hi;
        }
        #pragma unroll
        for (int j = 0; j < 16; j++) v[j] += __shfl_xor_sync(0xffffffffu, v[j], 16);
        #pragma unroll
        for (int stride = 8; stride >= 1; stride >>= 1) {
            #pragma unroll
            for (int j = 0; j < stride; j++) {
                float send = (lane & stride) ? v[j] : v[j + stride];
                float recv = __shfl_xor_sync(0xffffffffu, send, stride);
                v[j] = ((lane & stride) ? v[j + stride] : v[j]) + recv;
            }
        }
        if (lane < 16) G[base + lane] = v[0];
    }

    __syncthreads();
    if (warp != 0) return;

    // ---------------- Phase 2: Jacobi + entropy (warp 0) ----------------
    // All 32 lanes run; groups of 8 lanes compute identical copies (j = lane&7)
    // to avoid divergence; only lane 0 stores.
    const unsigned FULL = 0xffffffffu;
    const int j = lane & 7;

    float a[8];
    #pragma unroll
    for (int k = 0; k < 8; k++) a[k] = G[k * 8 + j];

    int prt8[7];
    #pragma unroll
    for (int r = 0; r < 7; r++)
        prt8[r] = (j == r) ? 7 : ((j == 7) ? r : ((2 * r + 14 - j) % 7));

    #pragma unroll 1
    for (int sw = 0; sw < SW8; sw++) {
        #pragma unroll
        for (int r = 0; r < 7; r++) {
            const int partner = prt8[r];
            float n0 = 0.f, n1 = 0.f;
            #pragma unroll
            for (int k = 0; k < 4; k++) n0 = fmaf(a[k], a[k], n0);
            #pragma unroll
            for (int k = 4; k < 8; k++) n1 = fmaf(a[k], a[k], n1);
            float n = n0 + n1;
            float bc[8];
            #pragma unroll
            for (int k = 0; k < 8; k++) bc[k] = __shfl_sync(FULL, a[k], partner, 8);
            float bn = __shfl_sync(FULL, n, partner, 8);
            float g0 = 0.f, g1 = 0.f;
            #pragma unroll
            for (int k = 0; k < 4; k++) g0 = fmaf(a[k], bc[k], g0);
            #pragma unroll
            for (int k = 4; k < 8; k++) g1 = fmaf(a[k], bc[k], g1);
            float ga = g0 + g1;
            float c, s;
            rot_params(n, bn, ga, c, s);
            #pragma unroll
            for (int k = 0; k < 8; k++) a[k] = fmaf(c, a[k], -s * bc[k]);
        }
    }
    float sq8 = EPSF;
    #pragma unroll
    for (int k = 0; k < 8; k++) sq8 = fmaf(a[k], a[k], sq8);
    float T8 = sq8;
    #pragma unroll
    for (int m = 4; m >= 1; m >>= 1) T8 += __shfl_xor_sync(FULL, T8, m, 8);
    float p8 = sq8 * __fdividef(1.f, T8);
    float s8 = p8 * __logf(p8 + EPSF);
    #pragma unroll
    for (int m = 4; m >= 1; m >>= 1) s8 += __shfl_xor_sync(FULL, s8, m, 8);
    // S_whole = -s8 (all lanes in the group agree)

    // ---- both 4x4s: within each 8-lane group, lanes 0-3 -> ML, 4-7 -> MR ----
    const int j4  = j & 3;
    const int isR = j >> 2;
    const float* mb = G + 64 + isR * 16;
    float m4[4];
    #pragma unroll
    for (int k = 0; k < 4; k++) m4[k] = mb[k * 4 + j4];

    int prt4[3];
    #pragma unroll
    for (int r = 0; r < 3; r++)
        prt4[r] = (j4 == r) ? 3 : ((j4 == 3) ? r : ((2 * r + 6 - j4) % 3));

    #pragma unroll 1
    for (int sw = 0; sw < SW4; sw++) {
        #pragma unroll
        for (int r = 0; r < 3; r++) {
            const int partner = prt4[r];
            float n0 = fmaf(m4[0], m4[0], 0.f); n0 = fmaf(m4[1], m4[1], n0);
            float n1 = fmaf(m4[2], m4[2], 0.f); n1 = fmaf(m4[3], m4[3], n1);
            float n = n0 + n1;
            float bc[4];
            #pragma unroll
            for (int k = 0; k < 4; k++) bc[k] = __shfl_sync(FULL, m4[k], partner, 4);
            float bn = __shfl_sync(FULL, n, partner, 4);
            float g0 = fmaf(m4[0], bc[0], 0.f); g0 = fmaf(m4[1], bc[1], g0);
            float g1 = fmaf(m4[2], bc[2], 0.f); g1 = fmaf(m4[3], bc[3], g1);
            float ga = g0 + g1;
            float c, s;
            rot_params(n, bn, ga, c, s);
            #pragma unroll
            for (int k = 0; k < 4; k++) m4[k] = fmaf(c, m4[k], -s * bc[k]);
        }
    }
    float sq4 = EPSF;
    #pragma unroll
    for (int k = 0; k < 4; k++) sq4 = fmaf(m4[k], m4[k], sq4);
    float T4 = sq4;
    #pragma unroll
    for (int m = 2; m >= 1; m >>= 1) T4 += __shfl_xor_sync(FULL, T4, m, 4);
    float p4 = sq4 * __fdividef(1.f, T4);
    float s4 = p4 * __logf(p4 + EPSF);
    #pragma unroll
    for (int m = 2; m >= 1; m >>= 1) s4 += __shfl_xor_sync(FULL, s4, m, 4);
    // lanes 0-3 hold sum for ML, lanes 4-7 for MR (within the group)

    float s4R = __shfl_sync(FULL, s4, 4, 8);   // lane 0 reads MR's sum from lane 4
    if (lane == 0) {
        // phi = S_whole - S_left - S_right = -s8 + s4(L) + s4(R)
        float phi = -s8 + s4 + s4R;
        out[b] = phi > 0.f ? phi : 0.f;
    }
}

extern "C" void kernel_launch(void* const* d_in, const int* in_sizes, int n_in,
                              void* d_out, int out_size) {
    const float* sites = (const float*)d_in[0];
    float* out = (float*)d_out;
    phi_q_fused<<<BATCH, 128>>>(sites, out);
}

// round 12
// speedup vs baseline: 1.8725x; 1.8725x over previous
#include <cuda_runtime.h>

#define BATCH   8192
#define KDIM    256
#define EPSF    1e-10f
#define SW8     4
#define SW4     3

// Packed fp32x2 ops (Blackwell): only reachable via PTX.
#define FMA_F32X2(d, a, b, c) \
    asm("fma.rn.f32x2 %0, %1, %2, %3;" : "=l"(d) : "l"(a), "l"(b), "l"(c))
#define MUL_F32X2(d, a, b) \
    asm("mul.rn.f32x2 %0, %1, %2;" : "=l"(d) : "l"(a), "l"(b))
#define UNPACK_F32X2(lo, hi, in) do {                                   \
    unsigned _ulo, _uhi;                                                \
    asm("mov.b64 {%0, %1}, %2;" : "=r"(_ulo), "=r"(_uhi) : "l"(in));    \
    lo = __uint_as_float(_ulo); hi = __uint_as_float(_uhi);             \
} while (0)

// Scratch, element-major [BATCH][96]:
// 0..63  -> M8[i][j] = dot(row i,   row 8+j)   (o = i*8+j)
// 64..79 -> ML[i][j] = dot(row i,   row 4+j)
// 80..95 -> MR[i][j] = dot(row 8+i, row 12+j)
__device__ float g_scratch[BATCH * 96];

// ---------------------------------------------------------------------------
// Kernel 1: cross-Gram blocks. One CTA/element, direct LDG.128, f32x2 FMAs.
// Warps 0/1 run TWO PASSES over their B rows (16 packed accs reused) to halve
// accumulator register pressure -> more resident CTAs -> latency hidden.
// ---------------------------------------------------------------------------
__global__ __launch_bounds__(128)
void gram_kernel(const float* __restrict__ sites) {
    const int b    = blockIdx.x;
    const int tid  = threadIdx.x;
    const int warp = tid >> 5;
    const int lane = tid & 31;

    // Row r = 256 floats = 64 x 16B. Lane owns chunks (lane) and (lane+32).
    const ulonglong2* S2 = (const ulonglong2*)(sites + (size_t)b * (16 * KDIM));

    if (warp < 2) {
        // M8 rows i = warp*4..warp*4+3 vs rows 8..15 -> 32 outputs
        ulonglong2 Ar[4][2];
        #pragma unroll
        for (int a = 0; a < 4; a++) {
            Ar[a][0] = S2[(warp * 4 + a) * 64 + lane];
            Ar[a][1] = S2[(warp * 4 + a) * 64 + lane + 32];
        }
        float v[32];
        #pragma unroll
        for (int half = 0; half < 2; half++) {
            unsigned long long acc[16];
            #pragma unroll
            for (int jj = 0; jj < 4; jj++) {
                const int row = 8 + half * 4 + jj;
                ulonglong2 B0 = S2[row * 64 + lane];
                ulonglong2 B1 = S2[row * 64 + lane + 32];
                #pragma unroll
                for (int a = 0; a < 4; a++) {
                    unsigned long long& d = acc[a * 4 + jj];
                    MUL_F32X2(d, Ar[a][0].x, B0.x);
                    FMA_F32X2(d, Ar[a][0].y, B0.y, d);
                    FMA_F32X2(d, Ar[a][1].x, B1.x, d);
                    FMA_F32X2(d, Ar[a][1].y, B1.y, d);
                }
            }
            #pragma unroll
            for (int a = 0; a < 4; a++)
                #pragma unroll
                for (int jj = 0; jj < 4; jj++) {
                    float lo, hi; UNPACK_F32X2(lo, hi, acc[a * 4 + jj]);
                    v[a * 8 + half * 4 + jj] = lo + hi;
                }
        }
        // Multi-value tree reduce: 32 lane-sums in 31 shfl; lane l ends with out l.
        #pragma unroll
        for (int stride = 16; stride >= 1; stride >>= 1) {
            #pragma unroll
            for (int j = 0; j < stride; j++) {
                float send = (lane & stride) ? v[j] : v[j + stride];
                float recv = __shfl_xor_sync(0xffffffffu, send, stride);
                v[j] = ((lane & stride) ? v[j + stride] : v[j]) + recv;
            }
        }
        g_scratch[b * 96 + warp * 32 + lane] = v[0];
    } else {
        // warp2: ML (rows 0-3 x 4-7); warp3: MR (rows 8-11 x 12-15) -> 16 outputs
        const int ra   = (warp == 2) ? 0 : 8;
        const int base = (warp == 2) ? 64 : 80;
        ulonglong2 Ar[4][2];
        #pragma unroll
        for (int a = 0; a < 4; a++) {
            Ar[a][0] = S2[(ra + a) * 64 + lane];
            Ar[a][1] = S2[(ra + a) * 64 + lane + 32];
        }
        unsigned long long acc[16];
        #pragma unroll
        for (int j = 0; j < 4; j++) {
            ulonglong2 B0 = S2[(ra + 4 + j) * 64 + lane];
            ulonglong2 B1 = S2[(ra + 4 + j) * 64 + lane + 32];
            #pragma unroll
            for (int a = 0; a < 4; a++) {
                unsigned long long& d = acc[a * 4 + j];
                MUL_F32X2(d, Ar[a][0].x, B0.x);
                FMA_F32X2(d, Ar[a][0].y, B0.y, d);
                FMA_F32X2(d, Ar[a][1].x, B1.x, d);
                FMA_F32X2(d, Ar[a][1].y, B1.y, d);
            }
        }
        float v[16];
        #pragma unroll
        for (int o = 0; o < 16; o++) {
            float lo, hi; UNPACK_F32X2(lo, hi, acc[o]);
            v[o] = lo + hi;
        }
        #pragma unroll
        for (int j = 0; j < 16; j++) v[j] += __shfl_xor_sync(0xffffffffu, v[j], 16);
        #pragma unroll
        for (int stride = 8; stride >= 1; stride >>= 1) {
            #pragma unroll
            for (int j = 0; j < stride; j++) {
                float send = (lane & stride) ? v[j] : v[j + stride];
                float recv = __shfl_xor_sync(0xffffffffu, send, stride);
                v[j] = ((lane & stride) ? v[j + stride] : v[j]) + recv;
            }
        }
        if (lane < 16) g_scratch[b * 96 + base + lane] = v[0];
    }
}

// ---------------------------------------------------------------------------
// Kernel 2: 8 lanes per element; one column per lane (one-sided Jacobi).
// (R10 version, measured 13.47us.)
// ---------------------------------------------------------------------------
__device__ __forceinline__ void rot_params(float al, float be, float ga,
                                           float& c, float& s) {
    float tau = (be - al) * __fdividef(0.5f, ga);
    float t = copysignf(1.f, tau) *
              __fdividef(1.f, fabsf(tau) + sqrtf(fmaf(tau, tau, 1.f)));
    t = (fabsf(ga) > 1e-30f) ? t : 0.f;
    c = rsqrtf(fmaf(t, t, 1.f));
    s = c * t;
}

__global__ __launch_bounds__(128)
void jacobi_kernel(float* __restrict__ out) {
    const unsigned FULL = 0xffffffffu;
    const int tid = threadIdx.x;
    const int j   = tid & 7;                        // my column (8x8)
    const int b   = blockIdx.x * 16 + (tid >> 3);   // element
    const float* base = g_scratch + b * 96;

    // ---- 8x8 ----
    float a[8];
    #pragma unroll
    for (int k = 0; k < 8; k++) a[k] = base[k * 8 + j];

    int prt8[7];
    #pragma unroll
    for (int r = 0; r < 7; r++)
        prt8[r] = (j == r) ? 7 : ((j == 7) ? r : ((2 * r + 14 - j) % 7));

    #pragma unroll 1
    for (int sw = 0; sw < SW8; sw++) {
        #pragma unroll
        for (int r = 0; r < 7; r++) {
            const int partner = prt8[r];
            float n0 = 0.f, n1 = 0.f;
            #pragma unroll
            for (int k = 0; k < 4; k++) n0 = fmaf(a[k], a[k], n0);
            #pragma unroll
            for (int k = 4; k < 8; k++) n1 = fmaf(a[k], a[k], n1);
            float n = n0 + n1;
            float bc[8];
            #pragma unroll
            for (int k = 0; k < 8; k++) bc[k] = __shfl_sync(FULL, a[k], partner, 8);
            float bn = __shfl_sync(FULL, n, partner, 8);
            float g0 = 0.f, g1 = 0.f;
            #pragma unroll
            for (int k = 0; k < 4; k++) g0 = fmaf(a[k], bc[k], g0);
            #pragma unroll
            for (int k = 4; k < 8; k++) g1 = fmaf(a[k], bc[k], g1);
            float ga = g0 + g1;
            float c, s;
            rot_params(n, bn, ga, c, s);
            #pragma unroll
            for (int k = 0; k < 8; k++) a[k] = fmaf(c, a[k], -s * bc[k]);
        }
    }
    float sq8 = EPSF;
    #pragma unroll
    for (int k = 0; k < 8; k++) sq8 = fmaf(a[k], a[k], sq8);
    float T8 = sq8;
    #pragma unroll
    for (int m = 4; m >= 1; m >>= 1) T8 += __shfl_xor_sync(FULL, T8, m, 8);
    float p8 = sq8 * __fdividef(1.f, T8);
    float s8 = p8 * __logf(p8 + EPSF);
    #pragma unroll
    for (int m = 4; m >= 1; m >>= 1) s8 += __shfl_xor_sync(FULL, s8, m, 8);
    // S_whole = -s8 (all 8 lanes agree)

    // ---- both 4x4s: lanes 0-3 -> ML, lanes 4-7 -> MR, width-4 shuffles ----
    const int j4  = j & 3;
    const int isR = j >> 2;
    const float* mb = base + 64 + isR * 16;
    float m4[4];
    #pragma unroll
    for (int k = 0; k < 4; k++) m4[k] = mb[k * 4 + j4];

    int prt4[3];
    #pragma unroll
    for (int r = 0; r < 3; r++)
        prt4[r] = (j4 == r) ? 3 : ((j4 == 3) ? r : ((2 * r + 6 - j4) % 3));

    #pragma unroll 1
    for (int sw = 0; sw < SW4; sw++) {
        #pragma unroll
        for (int r = 0; r < 3; r++) {
            const int partner = prt4[r];
            float n0 = fmaf(m4[0], m4[0], 0.f); n0 = fmaf(m4[1], m4[1], n0);
            float n1 = fmaf(m4[2], m4[2], 0.f); n1 = fmaf(m4[3], m4[3], n1);
            float n = n0 + n1;
            float bc[4];
            #pragma unroll
            for (int k = 0; k < 4; k++) bc[k] = __shfl_sync(FULL, m4[k], partner, 4);
            float bn = __shfl_sync(FULL, n, partner, 4);
            float g0 = fmaf(m4[0], bc[0], 0.f); g0 = fmaf(m4[1], bc[1], g0);
            float g1 = fmaf(m4[2], bc[2], 0.f); g1 = fmaf(m4[3], bc[3], g1);
            float ga = g0 + g1;
            float c, s;
            rot_params(n, bn, ga, c, s);
            #pragma unroll
            for (int k = 0; k < 4; k++) m4[k] = fmaf(c, m4[k], -s * bc[k]);
        }
    }
    float sq4 = EPSF;
    #pragma unroll
    for (int k = 0; k < 4; k++) sq4 = fmaf(m4[k], m4[k], sq4);
    float T4 = sq4;
    #pragma unroll
    for (int m = 2; m >= 1; m >>= 1) T4 += __shfl_xor_sync(FULL, T4, m, 4);
    float p4 = sq4 * __fdividef(1.f, T4);
    float s4 = p4 * __logf(p4 + EPSF);
    #pragma unroll
    for (int m = 2; m >= 1; m >>= 1) s4 += __shfl_xor_sync(FULL, s4, m, 4);
    // lanes 0-3 hold sum for ML, lanes 4-7 for MR

    float s4R = __shfl_sync(FULL, s4, 4, 8);   // lane 0 reads MR's sum from lane 4
    if (j == 0) {
        // phi = S_whole - S_left - S_right = -s8 + s4(L) + s4(R)
        float phi = -s8 + s4 + s4R;
        out[b] = phi > 0.f ? phi : 0.f;
    }
}

extern "C" void kernel_launch(void* const* d_in, const int* in_sizes, int n_in,
                              void* d_out, int out_size) {
    const float* sites = (const float*)d_in[0];
    float* out = (float*)d_out;
    gram_kernel<<<BATCH, 128>>>(sites);
    jacobi_kernel<<<BATCH / 16, 128>>>(out);
}

// round 13
// speedup vs baseline: 1.8831x; 1.0057x over previous
#include <cuda_runtime.h>

#define BATCH   8192
#define KDIM    256
#define EPSF    1e-10f
#define SW8     4
#define SW4     3

// Packed fp32x2 ops (Blackwell): only reachable via PTX.
#define FMA_F32X2(d, a, b, c) \
    asm("fma.rn.f32x2 %0, %1, %2, %3;" : "=l"(d) : "l"(a), "l"(b), "l"(c))
#define MUL_F32X2(d, a, b) \
    asm("mul.rn.f32x2 %0, %1, %2;" : "=l"(d) : "l"(a), "l"(b))
#define UNPACK_F32X2(lo, hi, in) do {                                   \
    unsigned _ulo, _uhi;                                                \
    asm("mov.b64 {%0, %1}, %2;" : "=r"(_ulo), "=r"(_uhi) : "l"(in));    \
    lo = __uint_as_float(_ulo); hi = __uint_as_float(_uhi);             \
} while (0)

// Scratch, element-major [BATCH][96]:
// 0..63  -> M8[i][j] = dot(row i,   row 8+j)   (o = i*8+j)
// 64..79 -> ML[i][j] = dot(row i,   row 4+j)
// 80..95 -> MR[i][j] = dot(row 8+i, row 12+j)
__device__ float g_scratch[BATCH * 96];

// ---------------------------------------------------------------------------
// Kernel 1: cross-Gram blocks, single-read smem staging.
// Warp w LDGs rows 4w..4w+3 (once, coalesced), stores them to smem AND keeps
// them in registers as its A operand. B tiles read from smem (LDS.128,
// conflict-free). DRAM traffic = exactly the 32MB input.
//   w0: A=rows0-3 (regs),  B=rows8-15 (smem)  -> M8[0..3][*]
//   w1: A=rows4-7 (regs),  B=rows8-15 (smem)  -> M8[4..7][*]
//   w2: A=rows8-11 (regs), B=rows12-15 (smem) -> MR
//   w3: A=rows0-3 (smem),  B=rows4-7  (smem)  -> ML
// ---------------------------------------------------------------------------
__global__ __launch_bounds__(128)
void gram_kernel(const float* __restrict__ sites) {
    const int b    = blockIdx.x;
    const int tid  = threadIdx.x;
    const int warp = tid >> 5;
    const int lane = tid & 31;

    __shared__ ulonglong2 sm4[16 * 64];   // 16 rows x 64 chunks of 16B = 16KB

    const ulonglong2* S2 = (const ulonglong2*)(sites + (size_t)b * (16 * KDIM));

    // Stage own 4 rows; keep in registers.
    ulonglong2 Ar[4][2];
    #pragma unroll
    for (int a = 0; a < 4; a++) {
        Ar[a][0] = S2[(warp * 4 + a) * 64 + lane];
        Ar[a][1] = S2[(warp * 4 + a) * 64 + lane + 32];
        sm4[(warp * 4 + a) * 64 + lane]      = Ar[a][0];
        sm4[(warp * 4 + a) * 64 + lane + 32] = Ar[a][1];
    }
    __syncthreads();

    if (warp < 2) {
        // M8 rows warp*4..warp*4+3 vs B rows 8..15 (smem) -> 32 outputs
        float v[32];
        #pragma unroll
        for (int j = 0; j < 8; j++) {
            ulonglong2 B0 = sm4[(8 + j) * 64 + lane];
            ulonglong2 B1 = sm4[(8 + j) * 64 + lane + 32];
            #pragma unroll
            for (int a = 0; a < 4; a++) {
                unsigned long long d;
                MUL_F32X2(d, Ar[a][0].x, B0.x);
                FMA_F32X2(d, Ar[a][0].y, B0.y, d);
                FMA_F32X2(d, Ar[a][1].x, B1.x, d);
                FMA_F32X2(d, Ar[a][1].y, B1.y, d);
                float lo, hi; UNPACK_F32X2(lo, hi, d);
                v[a * 8 + j] = lo + hi;
            }
        }
        // Multi-value tree reduce: lane l ends with output l in v[0].
        #pragma unroll
        for (int stride = 16; stride >= 1; stride >>= 1) {
            #pragma unroll
            for (int j = 0; j < stride; j++) {
                float send = (lane & stride) ? v[j] : v[j + stride];
                float recv = __shfl_xor_sync(0xffffffffu, send, stride);
                v[j] = ((lane & stride) ? v[j + stride] : v[j]) + recv;
            }
        }
        g_scratch[b * 96 + warp * 32 + lane] = v[0];
    } else {
        // w2: MR[i][j] = dot(row8+i, row12+j): A regs, B smem rows 12-15.
        // w3: ML[i][j] = dot(rowi,  row4+j):  A smem rows 0-3, B smem rows 4-7.
        ulonglong2 Aop[4][2];
        if (warp == 2) {
            #pragma unroll
            for (int a = 0; a < 4; a++) { Aop[a][0] = Ar[a][0]; Aop[a][1] = Ar[a][1]; }
        } else {
            #pragma unroll
            for (int a = 0; a < 4; a++) {
                Aop[a][0] = sm4[a * 64 + lane];
                Aop[a][1] = sm4[a * 64 + lane + 32];
            }
        }
        const int rb   = (warp == 2) ? 12 : 4;
        const int base = (warp == 2) ? 80 : 64;
        float v[16];
        #pragma unroll
        for (int j = 0; j < 4; j++) {
            ulonglong2 B0 = sm4[(rb + j) * 64 + lane];
            ulonglong2 B1 = sm4[(rb + j) * 64 + lane + 32];
            #pragma unroll
            for (int a = 0; a < 4; a++) {
                unsigned long long d;
                MUL_F32X2(d, Aop[a][0].x, B0.x);
                FMA_F32X2(d, Aop[a][0].y, B0.y, d);
                FMA_F32X2(d, Aop[a][1].x, B1.x, d);
                FMA_F32X2(d, Aop[a][1].y, B1.y, d);
                float lo, hi; UNPACK_F32X2(lo, hi, d);
                v[a * 4 + j] = lo + hi;
            }
        }
        #pragma unroll
        for (int j = 0; j < 16; j++) v[j] += __shfl_xor_sync(0xffffffffu, v[j], 16);
        #pragma unroll
        for (int stride = 8; stride >= 1; stride >>= 1) {
            #pragma unroll
            for (int j = 0; j < stride; j++) {
                float send = (lane & stride) ? v[j] : v[j + stride];
                float recv = __shfl_xor_sync(0xffffffffu, send, stride);
                v[j] = ((lane & stride) ? v[j + stride] : v[j]) + recv;
            }
        }
        if (lane < 16) g_scratch[b * 96 + base + lane] = v[0];
    }
}

// ---------------------------------------------------------------------------
// Kernel 2: 8 lanes per element, one column per lane (one-sided Jacobi).
// 8x8 and 4x4 rounds interleaved via macros inside fully-unrolled loops
// (all table indices compile-time -> register arrays, no dynamic ALU).
// ---------------------------------------------------------------------------
__device__ __forceinline__ void rot_params(float al, float be, float ga,
                                           float& c, float& s) {
    float tau = (be - al) * __fdividef(0.5f, ga);
    float t = copysignf(1.f, tau) *
              __fdividef(1.f, fabsf(tau) + sqrtf(fmaf(tau, tau, 1.f)));
    t = (fabsf(ga) > 1e-30f) ? t : 0.f;
    c = rsqrtf(fmaf(t, t, 1.f));
    s = c * t;
}

#define ROUND8(r) do {                                                        \
    const int partner = prt8[r];                                              \
    float n0 = 0.f, n1 = 0.f;                                                 \
    _Pragma("unroll")                                                         \
    for (int k = 0; k < 4; k++) n0 = fmaf(a[k], a[k], n0);                    \
    _Pragma("unroll")                                                         \
    for (int k = 4; k < 8; k++) n1 = fmaf(a[k], a[k], n1);                    \
    float n = n0 + n1;                                                        \
    float bc[8];                                                              \
    _Pragma("unroll")                                                         \
    for (int k = 0; k < 8; k++) bc[k] = __shfl_sync(FULL, a[k], partner, 8);  \
    float bn = __shfl_sync(FULL, n, partner, 8);                              \
    float g0 = 0.f, g1 = 0.f;                                                 \
    _Pragma("unroll")                                                         \
    for (int k = 0; k < 4; k++) g0 = fmaf(a[k], bc[k], g0);                   \
    _Pragma("unroll")                                                         \
    for (int k = 4; k < 8; k++) g1 = fmaf(a[k], bc[k], g1);                   \
    float ga = g0 + g1;                                                       \
    float c, s;                                                               \
    rot_params(n, bn, ga, c, s);                                              \
    _Pragma("unroll")                                                         \
    for (int k = 0; k < 8; k++) a[k] = fmaf(c, a[k], -s * bc[k]);             \
} while (0)

#define ROUND4(r) do {                                                        \
    const int partner = prt4[r];                                              \
    float n0 = fmaf(m4[0], m4[0], 0.f); n0 = fmaf(m4[1], m4[1], n0);          \
    float n1 = fmaf(m4[2], m4[2], 0.f); n1 = fmaf(m4[3], m4[3], n1);          \
    float n = n0 + n1;                                                        \
    float bc[4];                                                              \
    _Pragma("unroll")                                                         \
    for (int k = 0; k < 4; k++) bc[k] = __shfl_sync(FULL, m4[k], partner, 4); \
    float bn = __shfl_sync(FULL, n, partner, 4);                              \
    float g0 = fmaf(m4[0], bc[0], 0.f); g0 = fmaf(m4[1], bc[1], g0);          \
    float g1 = fmaf(m4[2], bc[2], 0.f); g1 = fmaf(m4[3], bc[3], g1);          \
    float ga = g0 + g1;                                                       \
    float c, s;                                                               \
    rot_params(n, bn, ga, c, s);                                              \
    _Pragma("unroll")                                                         \
    for (int k = 0; k < 4; k++) m4[k] = fmaf(c, m4[k], -s * bc[k]);           \
} while (0)

__global__ __launch_bounds__(128)
void jacobi_kernel(float* __restrict__ out) {
    const unsigned FULL = 0xffffffffu;
    const int tid = threadIdx.x;
    const int j   = tid & 7;                        // my column (8x8)
    const int b   = blockIdx.x * 16 + (tid >> 3);   // element
    const float* base = g_scratch + b * 96;

    // Load both problems upfront (independent latency chains).
    float a[8];
    #pragma unroll
    for (int k = 0; k < 8; k++) a[k] = base[k * 8 + j];

    const int j4  = j & 3;
    const int isR = j >> 2;                         // lanes 0-3 -> ML, 4-7 -> MR
    const float* mb = base + 64 + isR * 16;
    float m4[4];
    #pragma unroll
    for (int k = 0; k < 4; k++) m4[k] = mb[k * 4 + j4];

    int prt8[7];
    #pragma unroll
    for (int r = 0; r < 7; r++)
        prt8[r] = (j == r) ? 7 : ((j == 7) ? r : ((2 * r + 14 - j) % 7));
    int prt4[3];
    #pragma unroll
    for (int r = 0; r < 3; r++)
        prt4[r] = (j4 == r) ? 3 : ((j4 == 3) ? r : ((2 * r + 6 - j4) % 3));

    // 3 merged sweeps: 7 rounds of 8x8, rounds 0-2 carry a 4x4 round too.
    #pragma unroll 1
    for (int sw = 0; sw < 3; sw++) {
        #pragma unroll
        for (int r = 0; r < 7; r++) {
            ROUND8(r);
            if (r < 3) ROUND4(r);   // r is compile-time in the unrolled body
        }
    }
    // Final 8x8-only sweep (SW8=4 total; SW4=3 total already done).
    #pragma unroll
    for (int r = 0; r < 7; r++) ROUND8(r);

    // ---- entropies ----
    float sq8 = EPSF;
    #pragma unroll
    for (int k = 0; k < 8; k++) sq8 = fmaf(a[k], a[k], sq8);
    float T8 = sq8;
    #pragma unroll
    for (int m = 4; m >= 1; m >>= 1) T8 += __shfl_xor_sync(FULL, T8, m, 8);
    float p8 = sq8 * __fdividef(1.f, T8);
    float s8 = p8 * __logf(p8 + EPSF);
    #pragma unroll
    for (int m = 4; m >= 1; m >>= 1) s8 += __shfl_xor_sync(FULL, s8, m, 8);
    // S_whole = -s8

    float sq4 = EPSF;
    #pragma unroll
    for (int k = 0; k < 4; k++) sq4 = fmaf(m4[k], m4[k], sq4);
    float T4 = sq4;
    #pragma unroll
    for (int m = 2; m >= 1; m >>= 1) T4 += __shfl_xor_sync(FULL, T4, m, 4);
    float p4 = sq4 * __fdividef(1.f, T4);
    float s4 = p4 * __logf(p4 + EPSF);
    #pragma unroll
    for (int m = 2; m >= 1; m >>= 1) s4 += __shfl_xor_sync(FULL, s4, m, 4);
    // lanes 0-3: ML sum; lanes 4-7: MR sum

    float s4R = __shfl_sync(FULL, s4, 4, 8);   // lane 0 reads MR's sum from lane 4
    if (j == 0) {
        // phi = S_whole - S_left - S_right = -s8 + s4(L) + s4(R)
        float phi = -s8 + s4 + s4R;
        out[b] = phi > 0.f ? phi : 0.f;
    }
}

extern "C" void kernel_launch(void* const* d_in, const int* in_sizes, int n_in,
                              void* d_out, int out_size) {
    const float* sites = (const float*)d_in[0];
    float* out = (float*)d_out;
    gram_kernel<<<BATCH, 128>>>(sites);
    jacobi_kernel<<<BATCH / 16, 128>>>(out);
}